// round 3
// baseline (speedup 1.0000x reference)
#include <cuda_runtime.h>
#include <cuda_fp16.h>
#include <math.h>

#define MAXN 50048
#define MAXE 800000
#define KIN 128
#define HID 64
#define NH 8
#define C2 40
#define NEG 0.2f

// ---------------- scratch ----------------
__device__ __half g_h1h[MAXN * HID];   // pair layout: (f, f+32) at half2 index node*32+f
__device__ float g_alS1[MAXN * NH];
__device__ float g_alD1[MAXN * NH];
__device__ float g_hact[MAXN * HID];   // activated layer-1 output (fp32, feeds gemm2)
__device__ __half g_h2h[MAXN * C2];    // pair layout: (2c, 2c+1) at half2 index node*20+c
__device__ float g_alS2[MAXN];
__device__ float g_alD2[MAXN];
// CSR
__device__ int g_cnt[MAXN];            // must be zero at kernel_launch entry (restored by scan_k)
__device__ int g_rowstart[MAXN + 1];
__device__ int g_wcur[MAXN];
__device__ int g_eidx[MAXE];

// ---------------- CSR build ----------------
__global__ void count_k(const int* __restrict__ ei, int E) {
    int i = blockIdx.x * blockDim.x + threadIdx.x;
    if (i < E) atomicAdd(&g_cnt[ei[E + i]], 1);
}

// single block, 1024 threads: chunked scan + zero cnt for next call
__global__ void scan_k(int n) {
    __shared__ int ssum[1024];
    int t = threadIdx.x;
    int CH = (n + 1023) >> 10;
    int beg = t * CH;
    int end = min(beg + CH, n);
    int s = 0;
    for (int i = beg; i < end; i++) s += g_cnt[i];
    ssum[t] = s;
    __syncthreads();
#pragma unroll
    for (int o = 1; o < 1024; o <<= 1) {
        int v = 0;
        if (t >= o) v = ssum[t - o];
        __syncthreads();
        if (t >= o) ssum[t] += v;
        __syncthreads();
    }
    int run = ssum[t] - s;   // exclusive prefix of this chunk
    for (int i = beg; i < end; i++) {
        g_rowstart[i] = run;
        g_wcur[i] = run;
        run += g_cnt[i];
        g_cnt[i] = 0;        // restore invariant for next call
    }
    if (t == 1023) g_rowstart[n] = ssum[1023];
}

__global__ void scatter_k(const int* __restrict__ ei, int E) {
    int i = blockIdx.x * blockDim.x + threadIdx.x;
    if (i < E) {
        int dst = ei[E + i];
        int pos = atomicAdd(&g_wcur[dst], 1);
        g_eidx[pos] = ei[i];
    }
}

// ---------------- layer 1 GEMM: [N,128]@[128,64] + per-head logits ----------------
__global__ __launch_bounds__(256) void gemm1_k(
        const float* __restrict__ x, const float* __restrict__ topo,
        const float* __restrict__ W1,
        const float* __restrict__ a_src, const float* __restrict__ a_dst, int n) {
    extern __shared__ float smem[];
    float* sW  = smem;           // 128*64 floats (reused as sH after compute)
    float* sX  = smem + 8192;    // 64*128
    float* sLS = smem + 16384;   // 64*8
    float* sLD = smem + 16896;   // 64*8
    int t = threadIdx.x;
    int row0 = blockIdx.x * 64;
    for (int i = t; i < KIN * HID; i += 256) sW[i] = W1[i];
    for (int i = t; i < 64 * KIN; i += 256) {
        int r = i >> 7, c = i & 127;
        int gr = row0 + r;
        float v = 0.f;
        if (gr < n) v = (c < 120) ? x[gr * 120 + c] : topo[gr * 8 + (c - 120)];
        sX[i] = v;
    }
    for (int i = t; i < 512; i += 256) { sLS[i] = 0.f; sLD[i] = 0.f; }
    __syncthreads();

    int rg = t >> 4;      // rows rg*4..+3
    int cg = t & 15;      // cols cg*4..+3
    float acc[4][4];
#pragma unroll
    for (int r = 0; r < 4; r++)
#pragma unroll
        for (int c = 0; c < 4; c++) acc[r][c] = 0.f;

    const float4* sW4 = reinterpret_cast<const float4*>(sW);
#pragma unroll 4
    for (int k = 0; k < KIN; k++) {
        float4 wv = sW4[k * 16 + cg];
        float xv0 = sX[(rg * 4 + 0) * KIN + k];
        float xv1 = sX[(rg * 4 + 1) * KIN + k];
        float xv2 = sX[(rg * 4 + 2) * KIN + k];
        float xv3 = sX[(rg * 4 + 3) * KIN + k];
#define STEP(r, xv) \
        acc[r][0] += xv * wv.x; acc[r][1] += xv * wv.y; \
        acc[r][2] += xv * wv.z; acc[r][3] += xv * wv.w;
        STEP(0, xv0) STEP(1, xv1) STEP(2, xv2) STEP(3, xv3)
#undef STEP
    }

    // attention logit partials (from registers, fp32)
    int hd = cg >> 1;
    int off = (cg & 1) * 4;
#pragma unroll
    for (int r = 0; r < 4; r++) {
        int lr = rg * 4 + r;
        float ps = 0.f, pd = 0.f;
#pragma unroll
        for (int j = 0; j < 4; j++) {
            ps += acc[r][j] * a_src[hd * 8 + off + j];
            pd += acc[r][j] * a_dst[hd * 8 + off + j];
        }
        atomicAdd(&sLS[lr * 8 + hd], ps);
        atomicAdd(&sLD[lr * 8 + hd], pd);
    }
    __syncthreads();           // compute-loop reads of sW done; sLS/sLD complete
    // stage h into smem (reuse sW region) for pair-packed half2 output
    float* sH = sW;
#pragma unroll
    for (int r = 0; r < 4; r++) {
        int lr = rg * 4 + r;
#pragma unroll
        for (int j = 0; j < 4; j++) sH[lr * HID + cg * 4 + j] = acc[r][j];
    }
    __syncthreads();
    __half2* hp = reinterpret_cast<__half2*>(g_h1h);
    for (int i = t; i < 64 * 32; i += 256) {   // 2048 half2 values
        int r = i >> 5, p = i & 31;
        int gr = row0 + r;
        if (gr < n)
            hp[gr * 32 + p] = __floats2half2_rn(sH[r * HID + p], sH[r * HID + p + 32]);
    }
    for (int i = t; i < 512; i += 256) {
        int lr = i >> 3, h = i & 7;
        int gr = row0 + lr;
        if (gr < n) {
            g_alS1[gr * 8 + h] = sLS[i];
            g_alD1[gr * 8 + h] = sLD[i];
        }
    }
}

// ---------------- layer 1 aggregation: warp per dst node ----------------
__global__ __launch_bounds__(256) void agg1_k(const float* __restrict__ b1, int n) {
    int w = (blockIdx.x * blockDim.x + threadIdx.x) >> 5;
    if (w >= n) return;
    int l = threadIdx.x & 31;
    int h0 = l >> 3;
    float alD = (l < 8) ? g_alD1[w * 8 + l] : 0.f;
    int beg = g_rowstart[w], end = g_rowstart[w + 1];
    const __half2* hp = reinterpret_cast<const __half2*>(g_h1h);
    float acc0 = 0.f, acc1 = 0.f, sh = 0.f;
    // self loop
    {
        float a = (l < 8) ? g_alS1[w * 8 + l] : 0.f;
        float e = a + alD;
        e = e > 0.f ? e : NEG * e;
        float q = __expf(e);
        float p0 = __shfl_sync(0xFFFFFFFFu, q, h0);
        float p1 = __shfl_sync(0xFFFFFFFFu, q, h0 + 4);
        float2 f = __half22float2(hp[w * 32 + l]);
        acc0 += p0 * f.x;
        acc1 += p1 * f.y;
        if (l < 8) sh += q;
    }
    int j = beg;
    for (; j + 2 <= end; j += 2) {
        int s0 = g_eidx[j], s1 = g_eidx[j + 1];
        float a0 = (l < 8) ? g_alS1[s0 * 8 + l] : 0.f;
        float a1 = (l < 8) ? g_alS1[s1 * 8 + l] : 0.f;
        __half2 h0v = hp[s0 * 32 + l];
        __half2 h1v = hp[s1 * 32 + l];
        float e0 = a0 + alD; e0 = e0 > 0.f ? e0 : NEG * e0;
        float e1 = a1 + alD; e1 = e1 > 0.f ? e1 : NEG * e1;
        float q0 = __expf(e0), q1 = __expf(e1);
        float p00 = __shfl_sync(0xFFFFFFFFu, q0, h0);
        float p01 = __shfl_sync(0xFFFFFFFFu, q0, h0 + 4);
        float p10 = __shfl_sync(0xFFFFFFFFu, q1, h0);
        float p11 = __shfl_sync(0xFFFFFFFFu, q1, h0 + 4);
        float2 f0 = __half22float2(h0v);
        float2 f1 = __half22float2(h1v);
        acc0 += p00 * f0.x + p10 * f1.x;
        acc1 += p01 * f0.y + p11 * f1.y;
        if (l < 8) sh += q0 + q1;
    }
    if (j < end) {
        int s0 = g_eidx[j];
        float a0 = (l < 8) ? g_alS1[s0 * 8 + l] : 0.f;
        __half2 h0v = hp[s0 * 32 + l];
        float e0 = a0 + alD; e0 = e0 > 0.f ? e0 : NEG * e0;
        float q0 = __expf(e0);
        float p00 = __shfl_sync(0xFFFFFFFFu, q0, h0);
        float p01 = __shfl_sync(0xFFFFFFFFu, q0, h0 + 4);
        float2 f0 = __half22float2(h0v);
        acc0 += p00 * f0.x;
        acc1 += p01 * f0.y;
        if (l < 8) sh += q0;
    }
    float s0v = __shfl_sync(0xFFFFFFFFu, sh, h0);
    float s1v = __shfl_sync(0xFFFFFFFFu, sh, h0 + 4);
    float v0 = acc0 / s0v + b1[l];
    float v1 = acc1 / s1v + b1[32 + l];
    g_hact[w * HID + l]      = v0 > 0.f ? v0 : expm1f(v0);
    g_hact[w * HID + 32 + l] = v1 > 0.f ? v1 : expm1f(v1);
}

// ---------------- layer 2 GEMM: [N,64]@[64,40] + scalar logits ----------------
__global__ __launch_bounds__(160) void gemm2_k(
        const float* __restrict__ W2,
        const float* __restrict__ a_src2, const float* __restrict__ a_dst2, int n) {
    __shared__ float sW[HID * C2];
    __shared__ float sX[64 * HID];
    __shared__ float sLS[64];
    __shared__ float sLD[64];
    int t = threadIdx.x;
    int row0 = blockIdx.x * 64;
    for (int i = t; i < HID * C2; i += 160) sW[i] = W2[i];
    for (int i = t; i < 64 * HID; i += 160) {
        int r = i >> 6, c = i & 63;
        int gr = row0 + r;
        sX[i] = (gr < n) ? g_hact[gr * HID + c] : 0.f;
    }
    if (t < 64) { sLS[t] = 0.f; sLD[t] = 0.f; }
    __syncthreads();

    int cg = t % 10;
    int rg = t / 10;
    float acc[4][4];
#pragma unroll
    for (int r = 0; r < 4; r++)
#pragma unroll
        for (int c = 0; c < 4; c++) acc[r][c] = 0.f;

    const float4* sW4 = reinterpret_cast<const float4*>(sW);
#pragma unroll 4
    for (int k = 0; k < HID; k++) {
        float4 wv = sW4[k * 10 + cg];
        float xv0 = sX[(rg * 4 + 0) * HID + k];
        float xv1 = sX[(rg * 4 + 1) * HID + k];
        float xv2 = sX[(rg * 4 + 2) * HID + k];
        float xv3 = sX[(rg * 4 + 3) * HID + k];
#define STEP(r, xv) \
        acc[r][0] += xv * wv.x; acc[r][1] += xv * wv.y; \
        acc[r][2] += xv * wv.z; acc[r][3] += xv * wv.w;
        STEP(0, xv0) STEP(1, xv1) STEP(2, xv2) STEP(3, xv3)
#undef STEP
    }

    __half2* hp2 = reinterpret_cast<__half2*>(g_h2h);
#pragma unroll
    for (int r = 0; r < 4; r++) {
        int lr = rg * 4 + r;
        int gr = row0 + lr;
        float ps = 0.f, pd = 0.f;
#pragma unroll
        for (int j = 0; j < 4; j++) {
            int c = cg * 4 + j;
            ps += acc[r][j] * a_src2[c];
            pd += acc[r][j] * a_dst2[c];
        }
        if (gr < n) {
            hp2[gr * 20 + cg * 2]     = __floats2half2_rn(acc[r][0], acc[r][1]);
            hp2[gr * 20 + cg * 2 + 1] = __floats2half2_rn(acc[r][2], acc[r][3]);
        }
        atomicAdd(&sLS[lr], ps);
        atomicAdd(&sLD[lr], pd);
    }
    __syncthreads();
    if (t < 64) {
        int gr = row0 + t;
        if (gr < n) { g_alS2[gr] = sLS[t]; g_alD2[gr] = sLD[t]; }
    }
}

// ---------------- layer 2 aggregation + log_softmax (warp per node, lanes<20 hold 2 feats) ----------------
__global__ __launch_bounds__(256) void agg2_k(const float* __restrict__ b2,
                                              float* __restrict__ out, int n) {
    int w = (blockIdx.x * blockDim.x + threadIdx.x) >> 5;
    if (w >= n) return;
    int l = threadIdx.x & 31;
    bool act = l < 20;
    float alDv = g_alD2[w];
    int beg = g_rowstart[w], end = g_rowstart[w + 1];
    const __half2* hp = reinterpret_cast<const __half2*>(g_h2h);
    float accx = 0.f, accy = 0.f, s = 0.f;
    // self loop
    {
        float e = g_alS2[w] + alDv;
        e = e > 0.f ? e : NEG * e;
        float p = __expf(e);
        if (act) {
            float2 f = __half22float2(hp[w * 20 + l]);
            accx += p * f.x; accy += p * f.y;
        }
        s += p;
    }
    int j = beg;
    for (; j + 2 <= end; j += 2) {
        int s0 = g_eidx[j], s1 = g_eidx[j + 1];
        float e0 = g_alS2[s0] + alDv; e0 = e0 > 0.f ? e0 : NEG * e0;
        float e1 = g_alS2[s1] + alDv; e1 = e1 > 0.f ? e1 : NEG * e1;
        float p0 = __expf(e0), p1 = __expf(e1);
        if (act) {
            float2 f0 = __half22float2(hp[s0 * 20 + l]);
            float2 f1 = __half22float2(hp[s1 * 20 + l]);
            accx += p0 * f0.x + p1 * f1.x;
            accy += p0 * f0.y + p1 * f1.y;
        }
        s += p0 + p1;
    }
    if (j < end) {
        int s0 = g_eidx[j];
        float e0 = g_alS2[s0] + alDv; e0 = e0 > 0.f ? e0 : NEG * e0;
        float p0 = __expf(e0);
        if (act) {
            float2 f0 = __half22float2(hp[s0 * 20 + l]);
            accx += p0 * f0.x; accy += p0 * f0.y;
        }
        s += p0;
    }
    float inv = 1.f / s;   // s is lane-uniform: no reduction needed
    float v0 = act ? (accx * inv + b2[2 * l])     : -3.0e38f;
    float v1 = act ? (accy * inv + b2[2 * l + 1]) : -3.0e38f;
    float m = fmaxf(v0, v1);
#pragma unroll
    for (int o = 16; o; o >>= 1) m = fmaxf(m, __shfl_xor_sync(0xFFFFFFFFu, m, o));
    float se = act ? (__expf(v0 - m) + __expf(v1 - m)) : 0.f;
#pragma unroll
    for (int o = 16; o; o >>= 1) se += __shfl_xor_sync(0xFFFFFFFFu, se, o);
    float lse = logf(se) + m;
    if (act) {
        float2 o2; o2.x = v0 - lse; o2.y = v1 - lse;
        reinterpret_cast<float2*>(out)[w * 20 + l] = o2;
    }
}

// ---------------- launcher ----------------
extern "C" void kernel_launch(void* const* d_in, const int* in_sizes, int n_in,
                              void* d_out, int out_size) {
    const float* x    = (const float*)d_in[0];
    const float* topo = (const float*)d_in[1];
    const int*   ei   = (const int*)d_in[2];
    const float* W1   = (const float*)d_in[3];
    const float* a_s1 = (const float*)d_in[4];
    const float* a_d1 = (const float*)d_in[5];
    const float* b1   = (const float*)d_in[6];
    const float* W2   = (const float*)d_in[7];
    const float* a_s2 = (const float*)d_in[8];
    const float* a_d2 = (const float*)d_in[9];
    const float* b2   = (const float*)d_in[10];
    float* out = (float*)d_out;

    int n = in_sizes[0] / 120;
    int E = in_sizes[2] / 2;

    cudaFuncSetAttribute(gemm1_k, cudaFuncAttributeMaxDynamicSharedMemorySize, 70656);

    // CSR build (g_cnt is zero on entry; scan_k re-zeroes it for the next call)
    count_k<<<(E + 255) / 256, 256>>>(ei, E);
    scan_k<<<1, 1024>>>(n);
    scatter_k<<<(E + 255) / 256, 256>>>(ei, E);

    // layer 1
    gemm1_k<<<(n + 63) / 64, 256, 69632>>>(x, topo, W1, a_s1, a_d1, n);
    agg1_k<<<(n * 32 + 255) / 256, 256>>>(b1, n);

    // layer 2
    gemm2_k<<<(n + 63) / 64, 160>>>(W2, a_s2, a_d2, n);
    agg2_k<<<(n * 32 + 255) / 256, 256>>>(b2, out, n);
}

// round 4
// speedup vs baseline: 1.0577x; 1.0577x over previous
#include <cuda_runtime.h>
#include <math.h>

#define MAXN 50048
#define MAXE 800000
#define KIN 128
#define HID 64
#define NH 8
#define C2 40
#define NEG 0.2f
#define SXS 129   // padded sX stride (conflict-free)

// ---------------- scratch ----------------
__device__ float g_h1[MAXN * HID];
__device__ float g_alS1[MAXN * NH];
__device__ float g_alD1[MAXN * NH];
__device__ float g_hact[MAXN * HID];
__device__ float g_h2[MAXN * C2];
__device__ float g_alS2[MAXN];
__device__ float g_alD2[MAXN];
// CSR
__device__ int g_cnt[MAXN];
__device__ int g_incl[MAXN];
__device__ int g_rowstart[MAXN];
__device__ int g_wcur[MAXN];
__device__ int g_eidx[MAXE];
__device__ int g_bsum[64];
__device__ int g_bscan[64];

// ---------------- CSR build ----------------
__global__ void zero_cnt_k(int n) {
    int i = blockIdx.x * blockDim.x + threadIdx.x;
    if (i < n) g_cnt[i] = 0;
}

__global__ void count_k(const int* __restrict__ ei, int E) {
    int i = blockIdx.x * blockDim.x + threadIdx.x;
    if (i < E) atomicAdd(&g_cnt[ei[E + i]], 1);
}

__global__ void scanA_k(int n) {
    __shared__ int s[1024];
    int i = blockIdx.x * 1024 + threadIdx.x;
    s[threadIdx.x] = (i < n) ? g_cnt[i] : 0;
    __syncthreads();
#pragma unroll
    for (int o = 1; o < 1024; o <<= 1) {
        int t = 0;
        if (threadIdx.x >= o) t = s[threadIdx.x - o];
        __syncthreads();
        if (threadIdx.x >= o) s[threadIdx.x] += t;
        __syncthreads();
    }
    if (i < n) g_incl[i] = s[threadIdx.x];
    if (threadIdx.x == 1023) g_bsum[blockIdx.x] = s[1023];
}

__global__ void scanB_k(int nb) {
    __shared__ int s[64];
    int t = threadIdx.x;
    int own = (t < nb) ? g_bsum[t] : 0;
    s[t] = own;
    __syncthreads();
#pragma unroll
    for (int o = 1; o < 64; o <<= 1) {
        int v = 0;
        if (t >= o) v = s[t - o];
        __syncthreads();
        if (t >= o) s[t] += v;
        __syncthreads();
    }
    if (t < nb) g_bscan[t] = s[t] - own;   // exclusive prefix
}

__global__ void scanC_k(int n) {
    int i = blockIdx.x * blockDim.x + threadIdx.x;
    if (i < n) {
        int start = g_incl[i] - g_cnt[i] + g_bscan[i >> 10];
        g_rowstart[i] = start;
        g_wcur[i] = start;
    }
}

__global__ void scatter_k(const int* __restrict__ ei, int E) {
    int i = blockIdx.x * blockDim.x + threadIdx.x;
    if (i < E) {
        int dst = ei[E + i];
        int pos = atomicAdd(&g_wcur[dst], 1);
        g_eidx[pos] = ei[i];
    }
}

// ---------------- layer 1 GEMM: [N,128]@[128,64] + per-head logits ----------------
// 128 threads, 128 rows x 64 cols per block, 8x8 per thread.
// Thread t: colg = t&7 (cols colg*8..+7 == head colg), rowg = t>>3 (rows rowg*8..+7).
__global__ __launch_bounds__(128) void gemm1_k(
        const float* __restrict__ x, const float* __restrict__ topo,
        const float* __restrict__ W1,
        const float* __restrict__ a_src, const float* __restrict__ a_dst, int n) {
    extern __shared__ float smem[];
    float* sX = smem;                 // 128 * 129
    float* sW = smem + 128 * SXS;     // 128 * 64
    int t = threadIdx.x;
    int row0 = blockIdx.x * 128;

    // load W (coalesced float4)
    {
        const float4* W14 = reinterpret_cast<const float4*>(W1);
        float4* sW4 = reinterpret_cast<float4*>(sW);
        for (int i = t; i < KIN * HID / 4; i += 128) sW4[i] = W14[i];
    }
    // load X: thread t owns input column c=t for all 128 rows (coalesced gmem, conflict-free smem)
    {
        int c = t;
#pragma unroll 4
        for (int r = 0; r < 128; r++) {
            int gr = row0 + r;
            float v = 0.f;
            if (gr < n) v = (c < 120) ? x[gr * 120 + c] : topo[gr * 8 + (c - 120)];
            sX[r * SXS + c] = v;
        }
    }
    __syncthreads();

    int colg = t & 7;
    int rowg = t >> 3;
    float acc[8][8];
#pragma unroll
    for (int r = 0; r < 8; r++)
#pragma unroll
        for (int c = 0; c < 8; c++) acc[r][c] = 0.f;

    const float4* sW4 = reinterpret_cast<const float4*>(sW);
#pragma unroll 2
    for (int k = 0; k < KIN; k++) {
        float4 w0 = sW4[k * 16 + colg * 2];
        float4 w1 = sW4[k * 16 + colg * 2 + 1];
        float xv[8];
#pragma unroll
        for (int r = 0; r < 8; r++) xv[r] = sX[(rowg * 8 + r) * SXS + k];
#pragma unroll
        for (int r = 0; r < 8; r++) {
            acc[r][0] += xv[r] * w0.x; acc[r][1] += xv[r] * w0.y;
            acc[r][2] += xv[r] * w0.z; acc[r][3] += xv[r] * w0.w;
            acc[r][4] += xv[r] * w1.x; acc[r][5] += xv[r] * w1.y;
            acc[r][6] += xv[r] * w1.z; acc[r][7] += xv[r] * w1.w;
        }
    }

    // epilogue: write h1 + complete per-head logits (cols of this thread == head colg)
    float as[8], ad[8];
#pragma unroll
    for (int j = 0; j < 8; j++) { as[j] = a_src[colg * 8 + j]; ad[j] = a_dst[colg * 8 + j]; }
    float4* g_h1_4 = reinterpret_cast<float4*>(g_h1);
#pragma unroll
    for (int r = 0; r < 8; r++) {
        int gr = row0 + rowg * 8 + r;
        if (gr >= n) continue;
        float4 o0, o1;
        o0.x = acc[r][0]; o0.y = acc[r][1]; o0.z = acc[r][2]; o0.w = acc[r][3];
        o1.x = acc[r][4]; o1.y = acc[r][5]; o1.z = acc[r][6]; o1.w = acc[r][7];
        g_h1_4[gr * 16 + colg * 2]     = o0;
        g_h1_4[gr * 16 + colg * 2 + 1] = o1;
        float ps = 0.f, pd = 0.f;
#pragma unroll
        for (int j = 0; j < 8; j++) { ps += acc[r][j] * as[j]; pd += acc[r][j] * ad[j]; }
        g_alS1[gr * 8 + colg] = ps;
        g_alD1[gr * 8 + colg] = pd;
    }
}

// ---------------- layer 1 aggregation: warp per dst node, fused normalize+bias+ELU ----------------
__global__ __launch_bounds__(256) void agg1_k(const float* __restrict__ b1, int n) {
    int w = (blockIdx.x * blockDim.x + threadIdx.x) >> 5;
    if (w >= n) return;
    int l = threadIdx.x & 31;
    int h0 = l >> 3;
    float alD = (l < 8) ? g_alD1[w * 8 + l] : 0.f;
    int beg = g_rowstart[w], cnt = g_cnt[w];
    float acc0 = 0.f, acc1 = 0.f, sh = 0.f;
    // self loop
    {
        float alS = (l < 8) ? g_alS1[w * 8 + l] : 0.f;
        float e = alS + alD;
        e = e > 0.f ? e : NEG * e;
        float pl = __expf(e);
        float p0 = __shfl_sync(0xFFFFFFFFu, pl, h0);
        float p1 = __shfl_sync(0xFFFFFFFFu, pl, h0 + 4);
        acc0 += p0 * g_h1[w * HID + l];
        acc1 += p1 * g_h1[w * HID + 32 + l];
        if (l < 8) sh += pl;
    }
    for (int j = 0; j < cnt; j++) {
        int src = g_eidx[beg + j];
        float alS = (l < 8) ? g_alS1[src * 8 + l] : 0.f;
        float e = alS + alD;
        e = e > 0.f ? e : NEG * e;
        float pl = __expf(e);
        float p0 = __shfl_sync(0xFFFFFFFFu, pl, h0);
        float p1 = __shfl_sync(0xFFFFFFFFu, pl, h0 + 4);
        acc0 += p0 * g_h1[src * HID + l];
        acc1 += p1 * g_h1[src * HID + 32 + l];
        if (l < 8) sh += pl;
    }
    float s0 = __shfl_sync(0xFFFFFFFFu, sh, h0);
    float s1 = __shfl_sync(0xFFFFFFFFu, sh, h0 + 4);
    float v0 = acc0 / s0 + b1[l];
    float v1 = acc1 / s1 + b1[32 + l];
    g_hact[w * HID + l]      = v0 > 0.f ? v0 : expm1f(v0);
    g_hact[w * HID + 32 + l] = v1 > 0.f ? v1 : expm1f(v1);
}

// ---------------- layer 2 GEMM: [N,64]@[64,40] + scalar logits ----------------
__global__ __launch_bounds__(160) void gemm2_k(
        const float* __restrict__ W2,
        const float* __restrict__ a_src2, const float* __restrict__ a_dst2, int n) {
    __shared__ float sW[HID * C2];
    __shared__ float sX[64 * HID];
    __shared__ float sLS[64];
    __shared__ float sLD[64];
    int t = threadIdx.x;
    int row0 = blockIdx.x * 64;
    for (int i = t; i < HID * C2; i += 160) sW[i] = W2[i];
    for (int i = t; i < 64 * HID; i += 160) {
        int r = i >> 6, c = i & 63;
        int gr = row0 + r;
        sX[i] = (gr < n) ? g_hact[gr * HID + c] : 0.f;
    }
    if (t < 64) { sLS[t] = 0.f; sLD[t] = 0.f; }
    __syncthreads();

    int cg = t % 10;
    int rg = t / 10;
    float acc[4][4];
#pragma unroll
    for (int r = 0; r < 4; r++)
#pragma unroll
        for (int c = 0; c < 4; c++) acc[r][c] = 0.f;

    const float4* sW4 = reinterpret_cast<const float4*>(sW);
#pragma unroll 4
    for (int k = 0; k < HID; k++) {
        float4 wv = sW4[k * 10 + cg];
        float xv0 = sX[(rg * 4 + 0) * HID + k];
        float xv1 = sX[(rg * 4 + 1) * HID + k];
        float xv2 = sX[(rg * 4 + 2) * HID + k];
        float xv3 = sX[(rg * 4 + 3) * HID + k];
#define STEP(r, xv) \
        acc[r][0] += xv * wv.x; acc[r][1] += xv * wv.y; \
        acc[r][2] += xv * wv.z; acc[r][3] += xv * wv.w;
        STEP(0, xv0) STEP(1, xv1) STEP(2, xv2) STEP(3, xv3)
#undef STEP
    }

#pragma unroll
    for (int r = 0; r < 4; r++) {
        int lr = rg * 4 + r;
        int gr = row0 + lr;
        float ps = 0.f, pd = 0.f;
#pragma unroll
        for (int j = 0; j < 4; j++) {
            int c = cg * 4 + j;
            if (gr < n) g_h2[gr * C2 + c] = acc[r][j];
            ps += acc[r][j] * a_src2[c];
            pd += acc[r][j] * a_dst2[c];
        }
        atomicAdd(&sLS[lr], ps);
        atomicAdd(&sLD[lr], pd);
    }
    __syncthreads();
    if (t < 64) {
        int gr = row0 + t;
        if (gr < n) { g_alS2[gr] = sLS[t]; g_alD2[gr] = sLD[t]; }
    }
}

// ---------------- layer 2 aggregation + log_softmax (warp per node) ----------------
__global__ __launch_bounds__(256) void agg2_k(const float* __restrict__ b2,
                                              float* __restrict__ out, int n) {
    int w = (blockIdx.x * blockDim.x + threadIdx.x) >> 5;
    if (w >= n) return;
    int l = threadIdx.x & 31;
    float alDv = g_alD2[w];
    int beg = g_rowstart[w], cnt = g_cnt[w];
    float acc0 = 0.f, acc1 = 0.f, s = 0.f;
    // self loop
    {
        float e = g_alS2[w] + alDv;
        e = e > 0.f ? e : NEG * e;
        float p = __expf(e);
        acc0 += p * g_h2[w * C2 + l];
        if (l < 8) acc1 += p * g_h2[w * C2 + 32 + l];
        s += p;
    }
    for (int j = 0; j < cnt; j++) {
        int src = g_eidx[beg + j];
        float e = g_alS2[src] + alDv;
        e = e > 0.f ? e : NEG * e;
        float p = __expf(e);
        acc0 += p * g_h2[src * C2 + l];
        if (l < 8) acc1 += p * g_h2[src * C2 + 32 + l];
        s += p;
    }
    float inv = 1.f / s;
    float v0 = acc0 * inv + b2[l];
    float v1 = (l < 8) ? (acc1 * inv + b2[32 + l]) : -3.0e38f;
    float m = fmaxf(v0, v1);
#pragma unroll
    for (int o = 16; o; o >>= 1) m = fmaxf(m, __shfl_xor_sync(0xFFFFFFFFu, m, o));
    float se = __expf(v0 - m) + ((l < 8) ? __expf(v1 - m) : 0.f);
#pragma unroll
    for (int o = 16; o; o >>= 1) se += __shfl_xor_sync(0xFFFFFFFFu, se, o);
    float lse = logf(se) + m;
    out[w * C2 + l] = v0 - lse;
    if (l < 8) out[w * C2 + 32 + l] = v1 - lse;
}

// ---------------- launcher ----------------
extern "C" void kernel_launch(void* const* d_in, const int* in_sizes, int n_in,
                              void* d_out, int out_size) {
    const float* x    = (const float*)d_in[0];
    const float* topo = (const float*)d_in[1];
    const int*   ei   = (const int*)d_in[2];
    const float* W1   = (const float*)d_in[3];
    const float* a_s1 = (const float*)d_in[4];
    const float* a_d1 = (const float*)d_in[5];
    const float* b1   = (const float*)d_in[6];
    const float* W2   = (const float*)d_in[7];
    const float* a_s2 = (const float*)d_in[8];
    const float* a_d2 = (const float*)d_in[9];
    const float* b2   = (const float*)d_in[10];
    float* out = (float*)d_out;

    int n = in_sizes[0] / 120;
    int E = in_sizes[2] / 2;
    int nb = (n + 1023) >> 10;

    const int GEMM1_SMEM = (128 * SXS + 128 * 64) * 4;   // 98816
    cudaFuncSetAttribute(gemm1_k, cudaFuncAttributeMaxDynamicSharedMemorySize, GEMM1_SMEM);

    // CSR build
    zero_cnt_k<<<(n + 255) / 256, 256>>>(n);
    count_k<<<(E + 255) / 256, 256>>>(ei, E);
    scanA_k<<<nb, 1024>>>(n);
    scanB_k<<<1, 64>>>(nb);
    scanC_k<<<(n + 255) / 256, 256>>>(n);
    scatter_k<<<(E + 255) / 256, 256>>>(ei, E);

    // layer 1
    gemm1_k<<<(n + 127) / 128, 128, GEMM1_SMEM>>>(x, topo, W1, a_s1, a_d1, n);
    agg1_k<<<(n * 32 + 255) / 256, 256>>>(b1, n);

    // layer 2
    gemm2_k<<<(n + 63) / 64, 160>>>(W2, a_s2, a_d2, n);
    agg2_k<<<(n * 32 + 255) / 256, 256>>>(b2, out, n);
}

// round 5
// speedup vs baseline: 1.4506x; 1.3715x over previous
#include <cuda_runtime.h>
#include <math.h>

#define MAXN 50048
#define MAXE 800000
#define KIN 128
#define HID 64
#define NH 8
#define C2 40
#define NEG 0.2f
#define SXS 129   // padded sX stride

// ---------------- scratch ----------------
__device__ float g_h1[MAXN * HID];
__device__ float g_alS1[MAXN * NH];
__device__ float g_alD1[MAXN * NH];
__device__ float g_hact[MAXN * HID];
__device__ float g_h2[MAXN * C2];
__device__ float g_alS2[MAXN];
__device__ float g_alD2[MAXN];
// CSR
__device__ int g_cnt[MAXN];         // zero at entry (zero-init at load; scanC re-zeroes)
__device__ int g_incl[MAXN];
__device__ int g_rowstart[MAXN + 1];
__device__ int g_wcur[MAXN];
__device__ int g_eidx[MAXE];
__device__ int g_bsum[64];

// ---------------- CSR build ----------------
__global__ void count_k(const int* __restrict__ ei, int E) {
    int i = blockIdx.x * blockDim.x + threadIdx.x;
    if (i < E) atomicAdd(&g_cnt[ei[E + i]], 1);
}

__global__ void scanA_k(int n) {
    __shared__ int s[1024];
    int i = blockIdx.x * 1024 + threadIdx.x;
    s[threadIdx.x] = (i < n) ? g_cnt[i] : 0;
    __syncthreads();
#pragma unroll
    for (int o = 1; o < 1024; o <<= 1) {
        int t = 0;
        if (threadIdx.x >= o) t = s[threadIdx.x - o];
        __syncthreads();
        if (threadIdx.x >= o) s[threadIdx.x] += t;
        __syncthreads();
    }
    if (i < n) g_incl[i] = s[threadIdx.x];
    if (threadIdx.x == 1023) g_bsum[blockIdx.x] = s[1023];
}

// inlines the tiny block-prefix, writes rowstart/wcur, zeroes cnt for next call
__global__ void scanC_k(int n, int E) {
    int i = blockIdx.x * blockDim.x + threadIdx.x;
    if (i == 0) g_rowstart[n] = E;
    if (i < n) {
        int b = i >> 10;
        int base = 0;
        for (int k = 0; k < b; k++) base += g_bsum[k];
        int start = g_incl[i] - g_cnt[i] + base;
        g_rowstart[i] = start;
        g_wcur[i] = start;
        g_cnt[i] = 0;
    }
}

__global__ void scatter_k(const int* __restrict__ ei, int E) {
    int i = blockIdx.x * blockDim.x + threadIdx.x;
    if (i < E) {
        int dst = ei[E + i];
        int pos = atomicAdd(&g_wcur[dst], 1);
        g_eidx[pos] = ei[i];
    }
}

// ---------------- layer 1 GEMM: [N,128]@[128,64] + per-head logits (R2 4x4 + pad) ----------------
__global__ __launch_bounds__(256) void gemm1_k(
        const float* __restrict__ x, const float* __restrict__ topo,
        const float* __restrict__ W1,
        const float* __restrict__ a_src, const float* __restrict__ a_dst, int n) {
    extern __shared__ float smem[];
    float* sW  = smem;                     // 128*64 = 8192
    float* sX  = smem + 8192;              // 64*129 = 8256
    float* sLS = smem + 8192 + 8256;       // 512
    float* sLD = sLS + 512;                // 512
    int t = threadIdx.x;
    int row0 = blockIdx.x * 64;
    {
        const float4* W14 = reinterpret_cast<const float4*>(W1);
        float4* sW4w = reinterpret_cast<float4*>(sW);
        for (int i = t; i < KIN * HID / 4; i += 256) sW4w[i] = W14[i];
    }
    for (int i = t; i < 64 * KIN; i += 256) {
        int r = i >> 7, c = i & 127;
        int gr = row0 + r;
        float v = 0.f;
        if (gr < n) v = (c < 120) ? x[gr * 120 + c] : topo[gr * 8 + (c - 120)];
        sX[r * SXS + c] = v;
    }
    for (int i = t; i < 512; i += 256) { sLS[i] = 0.f; sLD[i] = 0.f; }
    __syncthreads();

    int rg = t >> 4;      // rows rg*4..+3
    int cg = t & 15;      // cols cg*4..+3
    float acc[4][4];
#pragma unroll
    for (int r = 0; r < 4; r++)
#pragma unroll
        for (int c = 0; c < 4; c++) acc[r][c] = 0.f;

    const float4* sW4 = reinterpret_cast<const float4*>(sW);
#pragma unroll 4
    for (int k = 0; k < KIN; k++) {
        float4 wv = sW4[k * 16 + cg];
        float xv0 = sX[(rg * 4 + 0) * SXS + k];
        float xv1 = sX[(rg * 4 + 1) * SXS + k];
        float xv2 = sX[(rg * 4 + 2) * SXS + k];
        float xv3 = sX[(rg * 4 + 3) * SXS + k];
#define STEP(r, xv) \
        acc[r][0] += xv * wv.x; acc[r][1] += xv * wv.y; \
        acc[r][2] += xv * wv.z; acc[r][3] += xv * wv.w;
        STEP(0, xv0) STEP(1, xv1) STEP(2, xv2) STEP(3, xv3)
#undef STEP
    }

    int hd = cg >> 1;
    int off = (cg & 1) * 4;
    float4* g_h1_4 = reinterpret_cast<float4*>(g_h1);
#pragma unroll
    for (int r = 0; r < 4; r++) {
        int lr = rg * 4 + r;
        int gr = row0 + lr;
        if (gr < n) {
            float4 o;
            o.x = acc[r][0]; o.y = acc[r][1]; o.z = acc[r][2]; o.w = acc[r][3];
            g_h1_4[gr * 16 + cg] = o;
        }
        float ps = 0.f, pd = 0.f;
#pragma unroll
        for (int j = 0; j < 4; j++) {
            ps += acc[r][j] * a_src[hd * 8 + off + j];
            pd += acc[r][j] * a_dst[hd * 8 + off + j];
        }
        atomicAdd(&sLS[lr * 8 + hd], ps);
        atomicAdd(&sLD[lr * 8 + hd], pd);
    }
    __syncthreads();
    for (int i = t; i < 512; i += 256) {
        int lr = i >> 3, h = i & 7;
        int gr = row0 + lr;
        if (gr < n) {
            g_alS1[gr * 8 + h] = sLS[i];
            g_alD1[gr * 8 + h] = sLD[i];
        }
    }
}

// ---------------- layer 1 aggregation: warp/node, 4 edges per iteration ----------------
// lane l: edge-slot eo=l>>3, head hh=l&7 for the logit phase; features l / l+32 for gather.
__global__ __launch_bounds__(256) void agg1_k(const float* __restrict__ b1, int n) {
    int w = (blockIdx.x * blockDim.x + threadIdx.x) >> 5;
    if (w >= n) return;
    int l = threadIdx.x & 31;
    int h0 = l >> 3;     // head owning feature l (and h0+4 owns l+32)
    int hh = l & 7;      // head this lane evaluates in the logit phase
    float alDh = g_alD1[w * 8 + hh];
    int beg = g_rowstart[w], end = g_rowstart[w + 1];
    float acc0 = 0.f, acc1 = 0.f, qsum = 0.f;
    // self loop
    {
        float a = g_alS1[w * 8 + hh] + alDh;
        a = a > 0.f ? a : NEG * a;
        float q = __expf(a);
        if (l < 8) qsum += q;
        float p0 = __shfl_sync(0xFFFFFFFFu, q, h0);
        float p1 = __shfl_sync(0xFFFFFFFFu, q, h0 + 4);
        acc0 += p0 * g_h1[w * HID + l];
        acc1 += p1 * g_h1[w * HID + 32 + l];
    }
    for (int j = beg; j < end; j += 4) {
        int jj = j + h0;                 // edge slot == h0
        bool valid = jj < end;
        int srcv = g_eidx[valid ? jj : j];
        float a = g_alS1[srcv * 8 + hh] + alDh;
        a = a > 0.f ? a : NEG * a;
        float q = valid ? __expf(a) : 0.f;
        qsum += q;
        int nleft = end - j;             // warp-uniform
#pragma unroll
        for (int e2 = 0; e2 < 4; e2++) {
            if (e2 >= nleft) break;      // warp-uniform
            float p0 = __shfl_sync(0xFFFFFFFFu, q, e2 * 8 + h0);
            float p1 = __shfl_sync(0xFFFFFFFFu, q, e2 * 8 + h0 + 4);
            int sv = __shfl_sync(0xFFFFFFFFu, srcv, e2 * 8);
            acc0 += p0 * g_h1[sv * HID + l];
            acc1 += p1 * g_h1[sv * HID + 32 + l];
        }
    }
    // reduce qsum over edge-slots (lanes sharing hh)
    qsum += __shfl_xor_sync(0xFFFFFFFFu, qsum, 8);
    qsum += __shfl_xor_sync(0xFFFFFFFFu, qsum, 16);
    float s0 = __shfl_sync(0xFFFFFFFFu, qsum, h0);       // head h0 total (lane h0: hh==h0)
    float s1 = __shfl_sync(0xFFFFFFFFu, qsum, h0 + 4);
    float v0 = acc0 / s0 + b1[l];
    float v1 = acc1 / s1 + b1[32 + l];
    g_hact[w * HID + l]      = v0 > 0.f ? v0 : expm1f(v0);
    g_hact[w * HID + 32 + l] = v1 > 0.f ? v1 : expm1f(v1);
}

// ---------------- layer 2 GEMM: [N,64]@[64,40] + scalar logits ----------------
__global__ __launch_bounds__(160) void gemm2_k(
        const float* __restrict__ W2,
        const float* __restrict__ a_src2, const float* __restrict__ a_dst2, int n) {
    __shared__ float sW[HID * C2];
    __shared__ float sX[64 * HID];
    __shared__ float sLS[64];
    __shared__ float sLD[64];
    int t = threadIdx.x;
    int row0 = blockIdx.x * 64;
    for (int i = t; i < HID * C2; i += 160) sW[i] = W2[i];
    for (int i = t; i < 64 * HID; i += 160) {
        int r = i >> 6, c = i & 63;
        int gr = row0 + r;
        sX[i] = (gr < n) ? g_hact[gr * HID + c] : 0.f;
    }
    if (t < 64) { sLS[t] = 0.f; sLD[t] = 0.f; }
    __syncthreads();

    int cg = t % 10;
    int rg = t / 10;
    float acc[4][4];
#pragma unroll
    for (int r = 0; r < 4; r++)
#pragma unroll
        for (int c = 0; c < 4; c++) acc[r][c] = 0.f;

    const float4* sW4 = reinterpret_cast<const float4*>(sW);
#pragma unroll 4
    for (int k = 0; k < HID; k++) {
        float4 wv = sW4[k * 10 + cg];
        float xv0 = sX[(rg * 4 + 0) * HID + k];
        float xv1 = sX[(rg * 4 + 1) * HID + k];
        float xv2 = sX[(rg * 4 + 2) * HID + k];
        float xv3 = sX[(rg * 4 + 3) * HID + k];
#define STEP(r, xv) \
        acc[r][0] += xv * wv.x; acc[r][1] += xv * wv.y; \
        acc[r][2] += xv * wv.z; acc[r][3] += xv * wv.w;
        STEP(0, xv0) STEP(1, xv1) STEP(2, xv2) STEP(3, xv3)
#undef STEP
    }

#pragma unroll
    for (int r = 0; r < 4; r++) {
        int lr = rg * 4 + r;
        int gr = row0 + lr;
        float ps = 0.f, pd = 0.f;
#pragma unroll
        for (int j = 0; j < 4; j++) {
            int c = cg * 4 + j;
            if (gr < n) g_h2[gr * C2 + c] = acc[r][j];
            ps += acc[r][j] * a_src2[c];
            pd += acc[r][j] * a_dst2[c];
        }
        atomicAdd(&sLS[lr], ps);
        atomicAdd(&sLD[lr], pd);
    }
    __syncthreads();
    if (t < 64) {
        int gr = row0 + t;
        if (gr < n) { g_alS2[gr] = sLS[t]; g_alD2[gr] = sLD[t]; }
    }
}

// ---------------- layer 2 aggregation + log_softmax: warp/node, 32 edges/iteration ----------------
__global__ __launch_bounds__(256) void agg2_k(const float* __restrict__ b2,
                                              float* __restrict__ out, int n) {
    int w = (blockIdx.x * blockDim.x + threadIdx.x) >> 5;
    if (w >= n) return;
    int l = threadIdx.x & 31;
    float alDv = g_alD2[w];
    int beg = g_rowstart[w], end = g_rowstart[w + 1];
    float acc0 = 0.f, acc1 = 0.f, ssum = 0.f;
    // self loop
    {
        float e = g_alS2[w] + alDv;
        e = e > 0.f ? e : NEG * e;
        float p = __expf(e);
        if (l == 0) ssum += p;
        acc0 += p * g_h2[w * C2 + l];
        if (l < 8) acc1 += p * g_h2[w * C2 + 32 + l];
    }
    for (int j = beg; j < end; j += 32) {
        int jj = j + l;
        bool valid = jj < end;
        int srcv = g_eidx[valid ? jj : j];
        float e = g_alS2[srcv] + alDv;
        e = e > 0.f ? e : NEG * e;
        float q = valid ? __expf(e) : 0.f;
        ssum += q;
        int m = min(32, end - j);        // warp-uniform
        for (int e2 = 0; e2 < m; e2++) {
            float pp = __shfl_sync(0xFFFFFFFFu, q, e2);
            int sv = __shfl_sync(0xFFFFFFFFu, srcv, e2);
            acc0 += pp * g_h2[sv * C2 + l];
            if (l < 8) acc1 += pp * g_h2[sv * C2 + 32 + l];
        }
    }
#pragma unroll
    for (int o = 16; o; o >>= 1) ssum += __shfl_xor_sync(0xFFFFFFFFu, ssum, o);
    float inv = 1.f / ssum;
    float v0 = acc0 * inv + b2[l];
    float v1 = (l < 8) ? (acc1 * inv + b2[32 + l]) : -3.0e38f;
    float m = fmaxf(v0, v1);
#pragma unroll
    for (int o = 16; o; o >>= 1) m = fmaxf(m, __shfl_xor_sync(0xFFFFFFFFu, m, o));
    float se = __expf(v0 - m) + ((l < 8) ? __expf(v1 - m) : 0.f);
#pragma unroll
    for (int o = 16; o; o >>= 1) se += __shfl_xor_sync(0xFFFFFFFFu, se, o);
    float lse = logf(se) + m;
    out[w * C2 + l] = v0 - lse;
    if (l < 8) out[w * C2 + 32 + l] = v1 - lse;
}

// ---------------- launcher ----------------
extern "C" void kernel_launch(void* const* d_in, const int* in_sizes, int n_in,
                              void* d_out, int out_size) {
    const float* x    = (const float*)d_in[0];
    const float* topo = (const float*)d_in[1];
    const int*   ei   = (const int*)d_in[2];
    const float* W1   = (const float*)d_in[3];
    const float* a_s1 = (const float*)d_in[4];
    const float* a_d1 = (const float*)d_in[5];
    const float* b1   = (const float*)d_in[6];
    const float* W2   = (const float*)d_in[7];
    const float* a_s2 = (const float*)d_in[8];
    const float* a_d2 = (const float*)d_in[9];
    const float* b2   = (const float*)d_in[10];
    float* out = (float*)d_out;

    int n = in_sizes[0] / 120;
    int E = in_sizes[2] / 2;
    int nb = (n + 1023) >> 10;

    const int GEMM1_SMEM = (8192 + 64 * SXS + 1024) * 4;   // 69888 B
    cudaFuncSetAttribute(gemm1_k, cudaFuncAttributeMaxDynamicSharedMemorySize, GEMM1_SMEM);

    // CSR build (g_cnt zero on entry; scanC restores)
    count_k<<<(E + 255) / 256, 256>>>(ei, E);
    scanA_k<<<nb, 1024>>>(n);
    scanC_k<<<(n + 255) / 256, 256>>>(n, E);
    scatter_k<<<(E + 255) / 256, 256>>>(ei, E);

    // layer 1
    gemm1_k<<<(n + 63) / 64, 256, GEMM1_SMEM>>>(x, topo, W1, a_s1, a_d1, n);
    agg1_k<<<(n * 32 + 255) / 256, 256>>>(b1, n);

    // layer 2
    gemm2_k<<<(n + 63) / 64, 160>>>(W2, a_s2, a_d2, n);
    agg2_k<<<(n * 32 + 255) / 256, 256>>>(b2, out, n);
}

// round 6
// speedup vs baseline: 1.4678x; 1.0118x over previous
#include <cuda_runtime.h>
#include <cuda_fp16.h>
#include <math.h>

#define MAXN 50048
#define MAXE 800000
#define KIN 128
#define HID 64
#define NH 8
#define C2 40
#define NEG 0.2f
#define SXS 129

// ---------------- scratch ----------------
__device__ __half g_h1h[MAXN * HID];    // natural layout [node][feat], fp16
__device__ float g_alS1[MAXN * NH];
__device__ float g_alD1[MAXN * NH];
__device__ float g_hact[MAXN * HID];    // fp32, feeds gemm2
__device__ __half g_h2h[MAXN * C2];     // natural layout [node][feat], fp16
__device__ float g_alS2[MAXN];
__device__ float g_alD2[MAXN];
// CSR
__device__ int g_cnt[MAXN];             // zero at entry (zero-init; scanC re-zeroes)
__device__ int g_incl[MAXN];
__device__ int g_rowstart[MAXN + 1];
__device__ int g_wcur[MAXN];
__device__ int g_eidx[MAXE];
__device__ int g_bsum[64];

// ---------------- CSR build (4-way MLP) ----------------
__global__ void count_k(const int* __restrict__ ei, int E, int T) {
    int gid = blockIdx.x * blockDim.x + threadIdx.x;
    int i0 = gid, i1 = gid + T, i2 = gid + 2 * T, i3 = gid + 3 * T;
    int d0 = (i0 < E) ? ei[E + i0] : -1;
    int d1 = (i1 < E) ? ei[E + i1] : -1;
    int d2 = (i2 < E) ? ei[E + i2] : -1;
    int d3 = (i3 < E) ? ei[E + i3] : -1;
    if (d0 >= 0) atomicAdd(&g_cnt[d0], 1);
    if (d1 >= 0) atomicAdd(&g_cnt[d1], 1);
    if (d2 >= 0) atomicAdd(&g_cnt[d2], 1);
    if (d3 >= 0) atomicAdd(&g_cnt[d3], 1);
}

__global__ void scanA_k(int n) {
    __shared__ int s[1024];
    int i = blockIdx.x * 1024 + threadIdx.x;
    s[threadIdx.x] = (i < n) ? g_cnt[i] : 0;
    __syncthreads();
#pragma unroll
    for (int o = 1; o < 1024; o <<= 1) {
        int t = 0;
        if (threadIdx.x >= o) t = s[threadIdx.x - o];
        __syncthreads();
        if (threadIdx.x >= o) s[threadIdx.x] += t;
        __syncthreads();
    }
    if (i < n) g_incl[i] = s[threadIdx.x];
    if (threadIdx.x == 1023) g_bsum[blockIdx.x] = s[1023];
}

__global__ void scanC_k(int n, int E) {
    int i = blockIdx.x * blockDim.x + threadIdx.x;
    if (i == 0) g_rowstart[n] = E;
    if (i < n) {
        int b = i >> 10;
        int base = 0;
        for (int k = 0; k < b; k++) base += g_bsum[k];
        int start = g_incl[i] - g_cnt[i] + base;
        g_rowstart[i] = start;
        g_wcur[i] = start;
        g_cnt[i] = 0;
    }
}

__global__ void scatter_k(const int* __restrict__ ei, int E, int T) {
    int gid = blockIdx.x * blockDim.x + threadIdx.x;
    int i0 = gid, i1 = gid + T, i2 = gid + 2 * T, i3 = gid + 3 * T;
    int d0 = (i0 < E) ? ei[E + i0] : -1;
    int s0 = (i0 < E) ? ei[i0] : 0;
    int d1 = (i1 < E) ? ei[E + i1] : -1;
    int s1 = (i1 < E) ? ei[i1] : 0;
    int d2 = (i2 < E) ? ei[E + i2] : -1;
    int s2 = (i2 < E) ? ei[i2] : 0;
    int d3 = (i3 < E) ? ei[E + i3] : -1;
    int s3 = (i3 < E) ? ei[i3] : 0;
    int p0 = (d0 >= 0) ? atomicAdd(&g_wcur[d0], 1) : 0;
    int p1 = (d1 >= 0) ? atomicAdd(&g_wcur[d1], 1) : 0;
    int p2 = (d2 >= 0) ? atomicAdd(&g_wcur[d2], 1) : 0;
    int p3 = (d3 >= 0) ? atomicAdd(&g_wcur[d3], 1) : 0;
    if (d0 >= 0) g_eidx[p0] = s0;
    if (d1 >= 0) g_eidx[p1] = s1;
    if (d2 >= 0) g_eidx[p2] = s2;
    if (d3 >= 0) g_eidx[p3] = s3;
}

// ---------------- layer 1 GEMM (R5 loop) + fp16 output ----------------
__global__ __launch_bounds__(256) void gemm1_k(
        const float* __restrict__ x, const float* __restrict__ topo,
        const float* __restrict__ W1,
        const float* __restrict__ a_src, const float* __restrict__ a_dst, int n) {
    extern __shared__ float smem[];
    float* sW  = smem;                     // 8192
    float* sX  = smem + 8192;              // 64*129
    float* sLS = smem + 8192 + 64 * SXS;   // 512
    float* sLD = sLS + 512;                // 512
    int t = threadIdx.x;
    int row0 = blockIdx.x * 64;
    {
        const float4* W14 = reinterpret_cast<const float4*>(W1);
        float4* sW4w = reinterpret_cast<float4*>(sW);
        for (int i = t; i < KIN * HID / 4; i += 256) sW4w[i] = W14[i];
    }
    for (int i = t; i < 64 * KIN; i += 256) {
        int r = i >> 7, c = i & 127;
        int gr = row0 + r;
        float v = 0.f;
        if (gr < n) v = (c < 120) ? x[gr * 120 + c] : topo[gr * 8 + (c - 120)];
        sX[r * SXS + c] = v;
    }
    for (int i = t; i < 512; i += 256) { sLS[i] = 0.f; sLD[i] = 0.f; }
    __syncthreads();

    int rg = t >> 4;
    int cg = t & 15;
    float acc[4][4];
#pragma unroll
    for (int r = 0; r < 4; r++)
#pragma unroll
        for (int c = 0; c < 4; c++) acc[r][c] = 0.f;

    const float4* sW4 = reinterpret_cast<const float4*>(sW);
#pragma unroll 4
    for (int k = 0; k < KIN; k++) {
        float4 wv = sW4[k * 16 + cg];
        float xv0 = sX[(rg * 4 + 0) * SXS + k];
        float xv1 = sX[(rg * 4 + 1) * SXS + k];
        float xv2 = sX[(rg * 4 + 2) * SXS + k];
        float xv3 = sX[(rg * 4 + 3) * SXS + k];
#define STEP(r, xv) \
        acc[r][0] += xv * wv.x; acc[r][1] += xv * wv.y; \
        acc[r][2] += xv * wv.z; acc[r][3] += xv * wv.w;
        STEP(0, xv0) STEP(1, xv1) STEP(2, xv2) STEP(3, xv3)
#undef STEP
    }

    int hd = cg >> 1;
    int off = (cg & 1) * 4;
    __half2* hp = reinterpret_cast<__half2*>(g_h1h);
#pragma unroll
    for (int r = 0; r < 4; r++) {
        int lr = rg * 4 + r;
        int gr = row0 + lr;
        if (gr < n) {
            hp[gr * 32 + cg * 2]     = __floats2half2_rn(acc[r][0], acc[r][1]);
            hp[gr * 32 + cg * 2 + 1] = __floats2half2_rn(acc[r][2], acc[r][3]);
        }
        float ps = 0.f, pd = 0.f;
#pragma unroll
        for (int j = 0; j < 4; j++) {
            ps += acc[r][j] * a_src[hd * 8 + off + j];
            pd += acc[r][j] * a_dst[hd * 8 + off + j];
        }
        atomicAdd(&sLS[lr * 8 + hd], ps);
        atomicAdd(&sLD[lr * 8 + hd], pd);
    }
    __syncthreads();
    for (int i = t; i < 512; i += 256) {
        int lr = i >> 3, h = i & 7;
        int gr = row0 + lr;
        if (gr < n) {
            g_alS1[gr * 8 + h] = sLS[i];
            g_alD1[gr * 8 + h] = sLD[i];
        }
    }
}

// ---------------- layer 1 aggregation: warp/node, fp16 gather ----------------
// lane l: feature pair (2l, 2l+1), head hh = l>>2. Lanes 0..7 compute logits for head l.
__global__ __launch_bounds__(256) void agg1_k(const float* __restrict__ b1, int n) {
    int w = (blockIdx.x * blockDim.x + threadIdx.x) >> 5;
    if (w >= n) return;
    int l = threadIdx.x & 31;
    int hh = l >> 2;
    float alD = (l < 8) ? g_alD1[w * 8 + l] : 0.f;
    int beg = g_rowstart[w], end = g_rowstart[w + 1];
    const __half2* hp = reinterpret_cast<const __half2*>(g_h1h);
    float ax = 0.f, ay = 0.f, qsum = 0.f;
    // self loop
    {
        float e = ((l < 8) ? g_alS1[w * 8 + l] : 0.f) + alD;
        e = e > 0.f ? e : NEG * e;
        float q = __expf(e);
        qsum += q;
        float p = __shfl_sync(0xFFFFFFFFu, q, hh);
        float2 f = __half22float2(hp[w * 32 + l]);
        ax += p * f.x; ay += p * f.y;
    }
    int j = beg;
    for (; j + 2 <= end; j += 2) {
        int s0 = g_eidx[j], s1 = g_eidx[j + 1];
        float e0 = ((l < 8) ? g_alS1[s0 * 8 + l] : 0.f) + alD;
        float e1 = ((l < 8) ? g_alS1[s1 * 8 + l] : 0.f) + alD;
        __half2 f0h = hp[s0 * 32 + l];
        __half2 f1h = hp[s1 * 32 + l];
        e0 = e0 > 0.f ? e0 : NEG * e0;
        e1 = e1 > 0.f ? e1 : NEG * e1;
        float q0 = __expf(e0), q1 = __expf(e1);
        qsum += q0 + q1;
        float p0 = __shfl_sync(0xFFFFFFFFu, q0, hh);
        float p1 = __shfl_sync(0xFFFFFFFFu, q1, hh);
        float2 f0 = __half22float2(f0h);
        float2 f1 = __half22float2(f1h);
        ax += p0 * f0.x + p1 * f1.x;
        ay += p0 * f0.y + p1 * f1.y;
    }
    if (j < end) {
        int s0 = g_eidx[j];
        float e0 = ((l < 8) ? g_alS1[s0 * 8 + l] : 0.f) + alD;
        __half2 f0h = hp[s0 * 32 + l];
        e0 = e0 > 0.f ? e0 : NEG * e0;
        float q0 = __expf(e0);
        qsum += q0;
        float p0 = __shfl_sync(0xFFFFFFFFu, q0, hh);
        float2 f0 = __half22float2(f0h);
        ax += p0 * f0.x; ay += p0 * f0.y;
    }
    float s = __shfl_sync(0xFFFFFFFFu, qsum, hh);   // lane h (h<8) holds head-h denom
    float v0 = ax / s + b1[2 * l];
    float v1 = ay / s + b1[2 * l + 1];
    float2 o;
    o.x = v0 > 0.f ? v0 : expm1f(v0);
    o.y = v1 > 0.f ? v1 : expm1f(v1);
    reinterpret_cast<float2*>(g_hact)[w * 32 + l] = o;
}

// ---------------- layer 2 GEMM (R5 loop) + fp16 output ----------------
__global__ __launch_bounds__(160) void gemm2_k(
        const float* __restrict__ W2,
        const float* __restrict__ a_src2, const float* __restrict__ a_dst2, int n) {
    __shared__ float sW[HID * C2];
    __shared__ float sX[64 * HID];
    __shared__ float sLS[64];
    __shared__ float sLD[64];
    int t = threadIdx.x;
    int row0 = blockIdx.x * 64;
    for (int i = t; i < HID * C2; i += 160) sW[i] = W2[i];
    for (int i = t; i < 64 * HID; i += 160) {
        int r = i >> 6, c = i & 63;
        int gr = row0 + r;
        sX[i] = (gr < n) ? g_hact[gr * HID + c] : 0.f;
    }
    if (t < 64) { sLS[t] = 0.f; sLD[t] = 0.f; }
    __syncthreads();

    int cg = t % 10;
    int rg = t / 10;
    float acc[4][4];
#pragma unroll
    for (int r = 0; r < 4; r++)
#pragma unroll
        for (int c = 0; c < 4; c++) acc[r][c] = 0.f;

    const float4* sW4 = reinterpret_cast<const float4*>(sW);
#pragma unroll 4
    for (int k = 0; k < HID; k++) {
        float4 wv = sW4[k * 10 + cg];
        float xv0 = sX[(rg * 4 + 0) * HID + k];
        float xv1 = sX[(rg * 4 + 1) * HID + k];
        float xv2 = sX[(rg * 4 + 2) * HID + k];
        float xv3 = sX[(rg * 4 + 3) * HID + k];
#define STEP(r, xv) \
        acc[r][0] += xv * wv.x; acc[r][1] += xv * wv.y; \
        acc[r][2] += xv * wv.z; acc[r][3] += xv * wv.w;
        STEP(0, xv0) STEP(1, xv1) STEP(2, xv2) STEP(3, xv3)
#undef STEP
    }

    __half2* hp2 = reinterpret_cast<__half2*>(g_h2h);
#pragma unroll
    for (int r = 0; r < 4; r++) {
        int lr = rg * 4 + r;
        int gr = row0 + lr;
        float ps = 0.f, pd = 0.f;
#pragma unroll
        for (int j = 0; j < 4; j++) {
            int c = cg * 4 + j;
            ps += acc[r][j] * a_src2[c];
            pd += acc[r][j] * a_dst2[c];
        }
        if (gr < n) {
            hp2[gr * 20 + cg * 2]     = __floats2half2_rn(acc[r][0], acc[r][1]);
            hp2[gr * 20 + cg * 2 + 1] = __floats2half2_rn(acc[r][2], acc[r][3]);
        }
        atomicAdd(&sLS[lr], ps);
        atomicAdd(&sLD[lr], pd);
    }
    __syncthreads();
    if (t < 64) {
        int gr = row0 + t;
        if (gr < n) { g_alS2[gr] = sLS[t]; g_alD2[gr] = sLD[t]; }
    }
}

// ---------------- layer 2 aggregation + log_softmax: warp/node, fp16 gather ----------------
__global__ __launch_bounds__(256) void agg2_k(const float* __restrict__ b2,
                                              float* __restrict__ out, int n) {
    int w = (blockIdx.x * blockDim.x + threadIdx.x) >> 5;
    if (w >= n) return;
    int l = threadIdx.x & 31;
    bool act = l < 20;
    float alDv = g_alD2[w];
    int beg = g_rowstart[w], end = g_rowstart[w + 1];
    const __half2* hp = reinterpret_cast<const __half2*>(g_h2h);
    float ax = 0.f, ay = 0.f, ssum = 0.f;
    // self loop
    {
        float e = g_alS2[w] + alDv;
        e = e > 0.f ? e : NEG * e;
        float p = __expf(e);
        ssum += p;
        if (act) {
            float2 f = __half22float2(hp[w * 20 + l]);
            ax += p * f.x; ay += p * f.y;
        }
    }
    int j = beg;
    for (; j + 2 <= end; j += 2) {
        int s0 = g_eidx[j], s1 = g_eidx[j + 1];
        float e0 = g_alS2[s0] + alDv;
        float e1 = g_alS2[s1] + alDv;
        __half2 f0h = act ? hp[s0 * 20 + l] : __half2();
        __half2 f1h = act ? hp[s1 * 20 + l] : __half2();
        e0 = e0 > 0.f ? e0 : NEG * e0;
        e1 = e1 > 0.f ? e1 : NEG * e1;
        float p0 = __expf(e0), p1 = __expf(e1);
        ssum += p0 + p1;
        if (act) {
            float2 f0 = __half22float2(f0h);
            float2 f1 = __half22float2(f1h);
            ax += p0 * f0.x + p1 * f1.x;
            ay += p0 * f0.y + p1 * f1.y;
        }
    }
    if (j < end) {
        int s0 = g_eidx[j];
        float e0 = g_alS2[s0] + alDv;
        e0 = e0 > 0.f ? e0 : NEG * e0;
        float p0 = __expf(e0);
        ssum += p0;
        if (act) {
            float2 f0 = __half22float2(hp[s0 * 20 + l]);
            ax += p0 * f0.x; ay += p0 * f0.y;
        }
    }
    float inv = 1.f / ssum;   // lane-uniform
    float v0 = act ? (ax * inv + b2[2 * l])     : -3.0e38f;
    float v1 = act ? (ay * inv + b2[2 * l + 1]) : -3.0e38f;
    float m = fmaxf(v0, v1);
#pragma unroll
    for (int o = 16; o; o >>= 1) m = fmaxf(m, __shfl_xor_sync(0xFFFFFFFFu, m, o));
    float se = act ? (__expf(v0 - m) + __expf(v1 - m)) : 0.f;
#pragma unroll
    for (int o = 16; o; o >>= 1) se += __shfl_xor_sync(0xFFFFFFFFu, se, o);
    float lse = logf(se) + m;
    if (act) {
        float2 o2; o2.x = v0 - lse; o2.y = v1 - lse;
        reinterpret_cast<float2*>(out)[w * 20 + l] = o2;
    }
}

// ---------------- launcher ----------------
extern "C" void kernel_launch(void* const* d_in, const int* in_sizes, int n_in,
                              void* d_out, int out_size) {
    const float* x    = (const float*)d_in[0];
    const float* topo = (const float*)d_in[1];
    const int*   ei   = (const int*)d_in[2];
    const float* W1   = (const float*)d_in[3];
    const float* a_s1 = (const float*)d_in[4];
    const float* a_d1 = (const float*)d_in[5];
    const float* b1   = (const float*)d_in[6];
    const float* W2   = (const float*)d_in[7];
    const float* a_s2 = (const float*)d_in[8];
    const float* a_d2 = (const float*)d_in[9];
    const float* b2   = (const float*)d_in[10];
    float* out = (float*)d_out;

    int n = in_sizes[0] / 120;
    int E = in_sizes[2] / 2;
    int nb = (n + 1023) >> 10;
    int T = (E + 3) / 4;                 // threads for 4-way edge kernels

    const int GEMM1_SMEM = (8192 + 64 * SXS + 1024) * 4;
    cudaFuncSetAttribute(gemm1_k, cudaFuncAttributeMaxDynamicSharedMemorySize, GEMM1_SMEM);

    // CSR build
    count_k<<<(T + 255) / 256, 256>>>(ei, E, T);
    scanA_k<<<nb, 1024>>>(n);
    scanC_k<<<(n + 255) / 256, 256>>>(n, E);
    scatter_k<<<(T + 255) / 256, 256>>>(ei, E, T);

    // layer 1
    gemm1_k<<<(n + 63) / 64, 256, GEMM1_SMEM>>>(x, topo, W1, a_s1, a_d1, n);
    agg1_k<<<(n * 32 + 255) / 256, 256>>>(b1, n);

    // layer 2
    gemm2_k<<<(n + 63) / 64, 160>>>(W2, a_s2, a_d2, n);
    agg2_k<<<(n * 32 + 255) / 256, 256>>>(b2, out, n);
}